// round 14
// baseline (speedup 1.0000x reference)
#include <cuda_runtime.h>
#include <cstdint>

// out[64,14336] = x[64,4096] @ dequant(W_int) + bias + x.sum(-1)*u
// tf32 mma.sync; non-uniform split-K=5 (560 CTAs -> 296 resident slots,
// wave-balanced: 296+264); 2-stage cp.async ring, 104KB smem -> 2 CTAs/SM;
// W raw int32 in smem -> I2F (exact in tf32); per-group scale folding on
// D-fragment columns; deterministic gmem partials + reduce kernel.

#define TOKS   64
#define INF    4096
#define OUTF   14336
#define KC     64
#define NTILE  128
#define NTILES (OUTF / NTILE)   // 112
#define SPLITK 5
#define NCTA   (NTILES * SPLITK) // 560
#define STAGES 2

// chunk ranges per split (group-aligned: even starts, even counts)
__device__ __constant__ int c_cstart[SPLITK] = {0, 14, 28, 40, 52};
__device__ __constant__ int c_ccnt[SPLITK]   = {14, 14, 12, 12, 12};

// smem strides (words): W stride % 32 == 8 -> 136 ; x stride % 32 == 8 -> 72
#define WSTR 136
#define XSTR 72
#define W_STAGE_WORDS (KC * WSTR)            // 8704
#define X_STAGE_WORDS (TOKS * XSTR)          // 4608
#define STAGE_WORDS   (W_STAGE_WORDS + X_STAGE_WORDS)   // 13312
#define STAGE_BYTES   (STAGE_WORDS * 4)                 // 53248
#define W_STAGE_BYTES (W_STAGE_WORDS * 4)               // 34816
#define SMEM_BYTES    (STAGES * STAGE_BYTES)            // 106496

__device__ float g_xtf[TOKS * INF];            // tf32-rounded x, k-pair-interleaved
__device__ float g_xsum[TOKS];
__device__ float g_part[SPLITK * TOKS * OUTF]; // split-K partials (18.4MB)

static __device__ __forceinline__ uint32_t f2tf(float f) {
    uint32_t r;
    asm("cvt.rna.tf32.f32 %0, %1;" : "=r"(r) : "f"(f));
    return r;
}
static __device__ __forceinline__ uint32_t smem_u32(const void* p) {
    uint32_t a;
    asm("{ .reg .u64 t; cvta.to.shared.u64 t, %1; cvt.u32.u64 %0, t; }" : "=r"(a) : "l"(p));
    return a;
}
static __device__ __forceinline__ void cpasync16(uint32_t dst, const void* src) {
    asm volatile("cp.async.cg.shared.global [%0], [%1], 16;" :: "r"(dst), "l"(src));
}
static __device__ __forceinline__ void mma8(float* d, const uint32_t* a, const uint32_t* b) {
    asm volatile(
        "mma.sync.aligned.m16n8k8.row.col.f32.tf32.tf32.f32 "
        "{%0,%1,%2,%3}, {%4,%5,%6,%7}, {%8,%9}, {%0,%1,%2,%3};"
        : "+f"(d[0]), "+f"(d[1]), "+f"(d[2]), "+f"(d[3])
        : "r"(a[0]), "r"(a[1]), "r"(a[2]), "r"(a[3]), "r"(b[0]), "r"(b[1]));
}

// ---------- prep: x -> tf32, k-pair-interleave; per-token row sums ----------
// 1024 threads/row: 4 elems each (latency fix vs R13's 4.8us).
// within each 8-block: original j stored at (j&3)*2 + (j>>2) -> (k,k+4) adjacent
__global__ void __launch_bounds__(1024) prep_kernel(const float* __restrict__ x) {
    const int row = blockIdx.x;
    const int t = threadIdx.x;
    const float* xr = x + row * INF;
    float s = 0.f;
    #pragma unroll
    for (int i = 0; i < INF / 1024; ++i) {
        const int k = t + i * 1024;
        const float v = xr[k];
        s += v;
        const int j = k & 7;
        const int pos = (k & ~7) + ((j & 3) * 2 + (j >> 2));
        g_xtf[row * INF + pos] = __uint_as_float(f2tf(v));
    }
    #pragma unroll
    for (int off = 16; off; off >>= 1) s += __shfl_xor_sync(0xffffffffu, s, off);
    __shared__ float red[32];
    if ((t & 31) == 0) red[t >> 5] = s;
    __syncthreads();
    if (t < 32) {
        float v = red[t];
        #pragma unroll
        for (int off = 16; off; off >>= 1) v += __shfl_xor_sync(0xffffffffu, v, off);
        if (t == 0) g_xsum[row] = v;
    }
}

// ---------- main GEMM (one split-K work unit per CTA) ----------
__global__ void __launch_bounds__(256, 2)
qbits_kernel(const int* __restrict__ W, const float* __restrict__ scales)
{
    extern __shared__ uint32_t smem[];
    const uint32_t sbase = smem_u32(smem);
    const int tid  = threadIdx.x;
    const int lane = tid & 31;
    const int warp = tid >> 5;          // 0..7
    const int wm   = warp >> 2;         // 0..1  (M: 32 rows)
    const int wn   = warp & 3;          // 0..3  (N: 32 cols)
    const int tile  = blockIdx.x % NTILES;
    const int split = blockIdx.x / NTILES;
    const int obase = tile * NTILE;
    const int cstart = c_cstart[split];
    const int nchunk = c_ccnt[split];
    const int kbase  = cstart * KC;

    // copy geometry (256 threads)
    const int*   wsrc = W + obase + (lane << 2);
    const float* xsrc = g_xtf + (tid >> 2) * INF + ((tid & 3) << 4);
    const uint32_t wdst_off = (uint32_t)((warp * WSTR + (lane << 2)) * 4);
    const uint32_t xdst_off = (uint32_t)(W_STAGE_BYTES +
                              (((tid >> 2) * XSTR + ((tid & 3) << 4)) * 4));

    float acc[2][4][4];   // scaled accumulators
    float accg[2][4][4];  // per-group raw accumulators
    #pragma unroll
    for (int mt = 0; mt < 2; ++mt)
        #pragma unroll
        for (int nt = 0; nt < 4; ++nt)
            #pragma unroll
            for (int j = 0; j < 4; ++j) { acc[mt][nt][j] = 0.f; accg[mt][nt][j] = 0.f; }

    auto issue = [&](int c, int s) {
        const int k0 = kbase + c * KC;
        const uint32_t wb = sbase + (uint32_t)(s * STAGE_BYTES);
        #pragma unroll
        for (int p = 0; p < 8; ++p)
            cpasync16(wb + wdst_off + (uint32_t)(p * 8 * WSTR * 4),
                      wsrc + (k0 + warp + 8 * p) * OUTF);
        #pragma unroll
        for (int i = 0; i < 4; ++i)
            cpasync16(wb + xdst_off + (uint32_t)(i * 16), xsrc + k0 + i * 4);
        asm volatile("cp.async.commit_group;" ::: "memory");
    };

    issue(0, 0);

    float2 sc2[4];        // per-D-column scales
    int st = 0;
    for (int c = 0; c < nchunk; ++c) {
        asm volatile("cp.async.wait_group 0;" ::: "memory");
        __syncthreads();
        if (c + 1 < nchunk) issue(c + 1, st ^ 1);

        const int gc = cstart + c;      // global chunk (cstart even -> parity ok)
        if ((gc & 1) == 0) {            // group start: fetch D-column scales
            const float* srow = scales + (gc >> 1) * OUTF + obase
                              + wn * 32 + 2 * (lane & 3);
            #pragma unroll
            for (int nt = 0; nt < 4; ++nt)
                sc2[nt] = __ldg((const float2*)(srow + nt * 8));
        }

        const uint32_t* ws  = smem + st * STAGE_WORDS;
        const float*    xsm = (const float*)(ws + W_STAGE_WORDS);

        #pragma unroll
        for (int ks = 0; ks < 8; ++ks) {
            const int kp = ks * 8 + 2 * (lane & 3);   // interleaved pair offset
            const int kk = ks * 8 + (lane & 3);
            uint32_t a[2][4];
            #pragma unroll
            for (int mt = 0; mt < 2; ++mt) {
                const int r = wm * 32 + mt * 16 + (lane >> 2);
                const float2 p0 = *(const float2*)(xsm + r * XSTR + kp);        // (a0,a2)
                const float2 p1 = *(const float2*)(xsm + (r + 8) * XSTR + kp);  // (a1,a3)
                a[mt][0] = __float_as_uint(p0.x);
                a[mt][1] = __float_as_uint(p1.x);
                a[mt][2] = __float_as_uint(p0.y);
                a[mt][3] = __float_as_uint(p1.y);
            }
            #pragma unroll
            for (int nt = 0; nt < 4; ++nt) {
                const int col = wn * 32 + nt * 8 + (lane >> 2);
                const int w0 = (int)ws[kk * WSTR + col];
                const int w1 = (int)ws[(kk + 4) * WSTR + col];
                uint32_t bb[2];
                bb[0] = __float_as_uint((float)w0);   // exact in tf32
                bb[1] = __float_as_uint((float)w1);
                mma8(accg[0][nt], a[0], bb);
                mma8(accg[1][nt], a[1], bb);
            }
        }

        if (gc & 1) {         // group end: fold per-D-column scale, reset raw acc
            #pragma unroll
            for (int mt = 0; mt < 2; ++mt)
                #pragma unroll
                for (int nt = 0; nt < 4; ++nt) {
                    acc[mt][nt][0] = fmaf(sc2[nt].x, accg[mt][nt][0], acc[mt][nt][0]);
                    acc[mt][nt][1] = fmaf(sc2[nt].y, accg[mt][nt][1], acc[mt][nt][1]);
                    acc[mt][nt][2] = fmaf(sc2[nt].x, accg[mt][nt][2], acc[mt][nt][2]);
                    acc[mt][nt][3] = fmaf(sc2[nt].y, accg[mt][nt][3], acc[mt][nt][3]);
                    accg[mt][nt][0] = 0.f; accg[mt][nt][1] = 0.f;
                    accg[mt][nt][2] = 0.f; accg[mt][nt][3] = 0.f;
                }
        }
        st ^= 1;
    }

    // ---- epilogue: write partial tile (reduce kernel adds bias/u) ----
    float* part = g_part + split * (TOKS * OUTF);
    #pragma unroll
    for (int mt = 0; mt < 2; ++mt) {
        #pragma unroll
        for (int jr = 0; jr < 2; ++jr) {
            const int row = wm * 32 + mt * 16 + (lane >> 2) + jr * 8;
            #pragma unroll
            for (int nt = 0; nt < 4; ++nt) {
                const int col = obase + wn * 32 + nt * 8 + 2 * (lane & 3);
                float2 o2;
                o2.x = acc[mt][nt][jr * 2 + 0];
                o2.y = acc[mt][nt][jr * 2 + 1];
                *(float2*)(part + row * OUTF + col) = o2;
            }
        }
    }
}

// ---------- reduce: out = sum(partials) + bias + xsum*u ----------
__global__ void __launch_bounds__(256)
reduce_kernel(const float* __restrict__ u, const float* __restrict__ bias,
              float* __restrict__ out)
{
    const int idx = blockIdx.x * 256 + threadIdx.x;       // over float4 units
    const int t   = idx / (OUTF / 4);
    const int c4  = (idx % (OUTF / 4)) * 4;
    const float xs = g_xsum[t];
    const int base = t * OUTF + c4;
    float4 s0 = *(const float4*)(g_part + 0 * TOKS * OUTF + base);
    float4 s1 = *(const float4*)(g_part + 1 * TOKS * OUTF + base);
    float4 s2 = *(const float4*)(g_part + 2 * TOKS * OUTF + base);
    float4 s3 = *(const float4*)(g_part + 3 * TOKS * OUTF + base);
    float4 s4 = *(const float4*)(g_part + 4 * TOKS * OUTF + base);
    const float4 bv = *(const float4*)(bias + c4);
    const float4 uv = *(const float4*)(u + c4);
    float4 r;
    r.x = ((s0.x + s1.x) + (s2.x + s3.x)) + s4.x + bv.x + xs * uv.x;
    r.y = ((s0.y + s1.y) + (s2.y + s3.y)) + s4.y + bv.y + xs * uv.y;
    r.z = ((s0.z + s1.z) + (s2.z + s3.z)) + s4.z + bv.z + xs * uv.z;
    r.w = ((s0.w + s1.w) + (s2.w + s3.w)) + s4.w + bv.w + xs * uv.w;
    *(float4*)(out + base) = r;
}

extern "C" void kernel_launch(void* const* d_in, const int* in_sizes, int n_in,
                              void* d_out, int out_size) {
    const float* x  = (const float*)d_in[0];
    const int*   W  = (const int*)d_in[1];
    const float* sc = (const float*)d_in[2];
    const float* u  = (const float*)d_in[3];
    const float* b  = (const float*)d_in[4];
    float* out = (float*)d_out;

    cudaFuncSetAttribute(qbits_kernel, cudaFuncAttributeMaxDynamicSharedMemorySize,
                         SMEM_BYTES);
    prep_kernel<<<TOKS, 1024>>>(x);
    qbits_kernel<<<NCTA, 256, SMEM_BYTES>>>(W, sc);
    reduce_kernel<<<(TOKS * OUTF / 4) / 256, 256>>>(u, b, out);
}

// round 15
// speedup vs baseline: 1.0087x; 1.0087x over previous
#include <cuda_runtime.h>
#include <cstdint>

// out[64,14336] = x[64,4096] @ dequant(W_int) + bias + x.sum(-1)*u
// tf32 mma.sync; 296 PERSISTENT CTAs (2/SM), each owns a balanced contiguous
// range of global chunk-jobs (24-26 chunks), crossing tile boundaries with
// accumulator flush to <=4 deterministic partial layers; cp.async 2-stage ring
// pipelines across boundaries. W raw int32 -> I2F (exact in tf32); per-group
// scale fold on D-fragment columns. Reduce sums count(t) layers + bias + xsum*u.

#define TOKS   64
#define INF    4096
#define OUTF   14336
#define KC     64
#define NTILE  128
#define NTILES (OUTF / NTILE)   // 112
#define NSLOT  296              // 148 SMs x 2 CTAs
#define GJOBS  (NTILES * (INF / KC))   // 7168
#define NLAYER 4
#define STAGES 2

// smem strides (words): W stride % 32 == 8 -> 136 ; x stride % 32 == 8 -> 72
#define WSTR 136
#define XSTR 72
#define W_STAGE_WORDS (KC * WSTR)            // 8704
#define X_STAGE_WORDS (TOKS * XSTR)          // 4608
#define STAGE_WORDS   (W_STAGE_WORDS + X_STAGE_WORDS)   // 13312
#define STAGE_BYTES   (STAGE_WORDS * 4)                 // 53248
#define W_STAGE_BYTES (W_STAGE_WORDS * 4)               // 34816
#define SMEM_BYTES    (STAGES * STAGE_BYTES)            // 106496

__device__ float g_xtf[TOKS * INF];            // tf32-rounded x, k-pair-interleaved
__device__ float g_xsp[TOKS][4];               // per-quarter-row partial sums
__device__ float g_part[NLAYER * TOKS * OUTF]; // partial layers (14.7MB)

// job-range arithmetic: lo_g(s) = floor(448*s/37) groups; lo(s) = 2*lo_g(s) chunks
static __device__ __forceinline__ int lo_job(int s) { return 2 * ((s * 448) / 37); }
static __device__ __forceinline__ int s_first(int t) { return (1184 * t + 484) / 448 - 1; }
static __device__ __forceinline__ int s_last(int t)  { return (1184 * t + 1183) / 448; }

static __device__ __forceinline__ uint32_t f2tf(float f) {
    uint32_t r;
    asm("cvt.rna.tf32.f32 %0, %1;" : "=r"(r) : "f"(f));
    return r;
}
static __device__ __forceinline__ uint32_t smem_u32(const void* p) {
    uint32_t a;
    asm("{ .reg .u64 t; cvta.to.shared.u64 t, %1; cvt.u32.u64 %0, t; }" : "=r"(a) : "l"(p));
    return a;
}
static __device__ __forceinline__ void cpasync16(uint32_t dst, const void* src) {
    asm volatile("cp.async.cg.shared.global [%0], [%1], 16;" :: "r"(dst), "l"(src));
}
static __device__ __forceinline__ void mma8(float* d, const uint32_t* a, const uint32_t* b) {
    asm volatile(
        "mma.sync.aligned.m16n8k8.row.col.f32.tf32.tf32.f32 "
        "{%0,%1,%2,%3}, {%4,%5,%6,%7}, {%8,%9}, {%0,%1,%2,%3};"
        : "+f"(d[0]), "+f"(d[1]), "+f"(d[2]), "+f"(d[3])
        : "r"(a[0]), "r"(a[1]), "r"(a[2]), "r"(a[3]), "r"(b[0]), "r"(b[1]));
}

// ---------- prep: x -> tf32 + k-pair interleave; quarter-row partial sums ----------
// 256 blocks: row = b>>2, quarter = b&3 (1024 floats each, 4/thread).
// within each 8-block: original j stored at (j&3)*2 + (j>>2) -> (k,k+4) adjacent
__global__ void __launch_bounds__(256) prep_kernel(const float* __restrict__ x) {
    const int row = blockIdx.x >> 2;
    const int q   = blockIdx.x & 3;
    const int t   = threadIdx.x;
    const float* xr = x + row * INF + q * 1024;
    float s = 0.f;
    #pragma unroll
    for (int i = 0; i < 4; ++i) {
        const int kq = t + i * 256;
        const float v = xr[kq];
        s += v;
        const int k = q * 1024 + kq;
        const int j = k & 7;
        const int pos = (k & ~7) + ((j & 3) * 2 + (j >> 2));
        g_xtf[row * INF + pos] = __uint_as_float(f2tf(v));
    }
    #pragma unroll
    for (int off = 16; off; off >>= 1) s += __shfl_xor_sync(0xffffffffu, s, off);
    __shared__ float red[8];
    if ((t & 31) == 0) red[t >> 5] = s;
    __syncthreads();
    if (t < 8) {
        float v = red[t];
        #pragma unroll
        for (int off = 4; off; off >>= 1) v += __shfl_xor_sync(0xffu, v, off);
        if (t == 0) g_xsp[row][q] = v;
    }
}

// ---------- main GEMM: persistent, job-range scheduled ----------
__global__ void __launch_bounds__(256, 2)
qbits_kernel(const int* __restrict__ W, const float* __restrict__ scales)
{
    extern __shared__ uint32_t smem[];
    const uint32_t sbase = smem_u32(smem);
    const int tid  = threadIdx.x;
    const int lane = tid & 31;
    const int warp = tid >> 5;          // 0..7
    const int wm   = warp >> 2;         // 0..1  (M: 32 rows)
    const int wn   = warp & 3;          // 0..3  (N: 32 cols)
    const int s    = blockIdx.x;
    const int jlo  = lo_job(s);
    const int jhi  = lo_job(s + 1);

    const uint32_t wdst_off = (uint32_t)((warp * WSTR + (lane << 2)) * 4);
    const uint32_t xdst_off = (uint32_t)(W_STAGE_BYTES +
                              (((tid >> 2) * XSTR + ((tid & 3) << 4)) * 4));
    const float* xsrc = g_xtf + (tid >> 2) * INF + ((tid & 3) << 4);

    float acc[2][4][4];   // scaled accumulators
    float accg[2][4][4];  // per-group raw accumulators
    #pragma unroll
    for (int mt = 0; mt < 2; ++mt)
        #pragma unroll
        for (int nt = 0; nt < 4; ++nt)
            #pragma unroll
            for (int j = 0; j < 4; ++j) { acc[mt][nt][j] = 0.f; accg[mt][nt][j] = 0.f; }

    // issue chunk-job j into stage sg (works across tile boundaries)
    auto issue = [&](int j, int sg) {
        const int tile = j >> 6;
        const int k0   = (j & 63) * KC;
        const int* wsrc = W + tile * NTILE + (lane << 2);
        const uint32_t wb = sbase + (uint32_t)(sg * STAGE_BYTES);
        #pragma unroll
        for (int p = 0; p < 8; ++p)
            cpasync16(wb + wdst_off + (uint32_t)(p * 8 * WSTR * 4),
                      wsrc + (k0 + warp + 8 * p) * OUTF);
        #pragma unroll
        for (int i = 0; i < 4; ++i)
            cpasync16(wb + xdst_off + (uint32_t)(i * 16), xsrc + k0 + i * 4);
        asm volatile("cp.async.commit_group;" ::: "memory");
    };

    issue(jlo, 0);

    float2 sc2[4];        // per-D-column scales
    int st = 0;
    for (int j = jlo; j < jhi; ++j) {
        asm volatile("cp.async.wait_group 0;" ::: "memory");
        __syncthreads();
        if (j + 1 < jhi) issue(j + 1, st ^ 1);

        const int tile = j >> 6;
        const int c    = j & 63;       // chunk within tile (segment starts even)
        if ((c & 1) == 0) {            // group start: fetch D-column scales
            const float* srow = scales + (c >> 1) * OUTF + tile * NTILE
                              + wn * 32 + 2 * (lane & 3);
            #pragma unroll
            for (int nt = 0; nt < 4; ++nt)
                sc2[nt] = __ldg((const float2*)(srow + nt * 8));
        }

        const uint32_t* ws  = smem + st * STAGE_WORDS;
        const float*    xsm = (const float*)(ws + W_STAGE_WORDS);

        #pragma unroll
        for (int ks = 0; ks < 8; ++ks) {
            const int kp = ks * 8 + 2 * (lane & 3);   // interleaved pair offset
            const int kk = ks * 8 + (lane & 3);
            uint32_t a[2][4];
            #pragma unroll
            for (int mt = 0; mt < 2; ++mt) {
                const int r = wm * 32 + mt * 16 + (lane >> 2);
                const float2 p0 = *(const float2*)(xsm + r * XSTR + kp);        // (a0,a2)
                const float2 p1 = *(const float2*)(xsm + (r + 8) * XSTR + kp);  // (a1,a3)
                a[mt][0] = __float_as_uint(p0.x);
                a[mt][1] = __float_as_uint(p1.x);
                a[mt][2] = __float_as_uint(p0.y);
                a[mt][3] = __float_as_uint(p1.y);
            }
            #pragma unroll
            for (int nt = 0; nt < 4; ++nt) {
                const int col = wn * 32 + nt * 8 + (lane >> 2);
                const int w0 = (int)ws[kk * WSTR + col];
                const int w1 = (int)ws[(kk + 4) * WSTR + col];
                uint32_t bb[2];
                bb[0] = __float_as_uint((float)w0);   // exact in tf32
                bb[1] = __float_as_uint((float)w1);
                mma8(accg[0][nt], a[0], bb);
                mma8(accg[1][nt], a[1], bb);
            }
        }

        if (c & 1) {          // group end: fold per-D-column scale, reset raw acc
            #pragma unroll
            for (int mt = 0; mt < 2; ++mt)
                #pragma unroll
                for (int nt = 0; nt < 4; ++nt) {
                    acc[mt][nt][0] = fmaf(sc2[nt].x, accg[mt][nt][0], acc[mt][nt][0]);
                    acc[mt][nt][1] = fmaf(sc2[nt].y, accg[mt][nt][1], acc[mt][nt][1]);
                    acc[mt][nt][2] = fmaf(sc2[nt].x, accg[mt][nt][2], acc[mt][nt][2]);
                    acc[mt][nt][3] = fmaf(sc2[nt].y, accg[mt][nt][3], acc[mt][nt][3]);
                    accg[mt][nt][0] = 0.f; accg[mt][nt][1] = 0.f;
                    accg[mt][nt][2] = 0.f; accg[mt][nt][3] = 0.f;
                }
        }

        // segment end (range end or tile boundary): flush partials, reset acc
        if (j + 1 == jhi || ((j + 1) & 63) == 0) {
            const int layer = s - s_first(tile);
            const int obase = tile * NTILE;
            float* part = g_part + layer * (TOKS * OUTF);
            #pragma unroll
            for (int mt = 0; mt < 2; ++mt)
                #pragma unroll
                for (int jr = 0; jr < 2; ++jr) {
                    const int row = wm * 32 + mt * 16 + (lane >> 2) + jr * 8;
                    #pragma unroll
                    for (int nt = 0; nt < 4; ++nt) {
                        const int col = obase + wn * 32 + nt * 8 + 2 * (lane & 3);
                        float2 o2;
                        o2.x = acc[mt][nt][jr * 2 + 0];
                        o2.y = acc[mt][nt][jr * 2 + 1];
                        *(float2*)(part + row * OUTF + col) = o2;
                        acc[mt][nt][jr * 2 + 0] = 0.f;
                        acc[mt][nt][jr * 2 + 1] = 0.f;
                    }
                }
        }
        st ^= 1;
    }
}

// ---------- reduce: out = sum(valid layers) + bias + xsum*u ----------
__global__ void __launch_bounds__(256)
reduce_kernel(const float* __restrict__ u, const float* __restrict__ bias,
              float* __restrict__ out)
{
    const int idx = blockIdx.x * 256 + threadIdx.x;       // over float4 units
    const int t   = idx / (OUTF / 4);
    const int c4  = (idx % (OUTF / 4)) * 4;
    const int tile = c4 >> 7;
    const int n = s_last(tile) - s_first(tile) + 1;       // 3 or 4 layers valid
    const float xs = (g_xsp[t][0] + g_xsp[t][1]) + (g_xsp[t][2] + g_xsp[t][3]);
    const int base = t * OUTF + c4;
    float4 s0 = *(const float4*)(g_part + 0 * TOKS * OUTF + base);
    float4 s1 = *(const float4*)(g_part + 1 * TOKS * OUTF + base);
    float4 s2 = *(const float4*)(g_part + 2 * TOKS * OUTF + base);
    float4 r;
    r.x = (s0.x + s1.x) + s2.x;
    r.y = (s0.y + s1.y) + s2.y;
    r.z = (s0.z + s1.z) + s2.z;
    r.w = (s0.w + s1.w) + s2.w;
    if (n == 4) {
        float4 s3 = *(const float4*)(g_part + 3 * TOKS * OUTF + base);
        r.x += s3.x; r.y += s3.y; r.z += s3.z; r.w += s3.w;
    }
    const float4 bv = *(const float4*)(bias + c4);
    const float4 uv = *(const float4*)(u + c4);
    r.x += bv.x + xs * uv.x;
    r.y += bv.y + xs * uv.y;
    r.z += bv.z + xs * uv.z;
    r.w += bv.w + xs * uv.w;
    *(float4*)(out + base) = r;
}

extern "C" void kernel_launch(void* const* d_in, const int* in_sizes, int n_in,
                              void* d_out, int out_size) {
    const float* x  = (const float*)d_in[0];
    const int*   W  = (const int*)d_in[1];
    const float* sc = (const float*)d_in[2];
    const float* u  = (const float*)d_in[3];
    const float* b  = (const float*)d_in[4];
    float* out = (float*)d_out;

    cudaFuncSetAttribute(qbits_kernel, cudaFuncAttributeMaxDynamicSharedMemorySize,
                         SMEM_BYTES);
    prep_kernel<<<TOKS * 4, 256>>>(x);
    qbits_kernel<<<NSLOT, 256, SMEM_BYTES>>>(W, sc);
    reduce_kernel<<<(TOKS * OUTF / 4) / 256, 256>>>(u, b, out);
}

// round 16
// speedup vs baseline: 1.1640x; 1.1539x over previous
#include <cuda_runtime.h>
#include <cstdint>

// out[64,14336] = x[64,4096] @ dequant(W_int) + bias + x.sum(-1)*u
// tf32 mma.sync; split-K=4 (448 CTAs over 148 SMs, 2 CTAs/SM resident);
// 2-stage cp.async ring; W raw int32 in smem -> I2F (exact in tf32);
// per-group scale fold on D-fragment columns; deterministic partials+reduce.
// R16: warp tile m64n16 (1Mx8N) -- eliminates the 2x duplication of B
// fragment load+convert that the m32n32 (2Mx4N) grid had (~420 -> ~230
// instr/warp/chunk).

#define TOKS   64
#define INF    4096
#define OUTF   14336
#define KC     64
#define NTILE  128
#define NTILES (OUTF / NTILE)   // 112
#define SPLITK 4
#define KPER   (INF / SPLITK)   // 1024
#define NCHUNK (KPER / KC)      // 16
#define NCTA   (NTILES * SPLITK) // 448
#define STAGES 2

// smem strides (words): W stride % 32 == 8 -> 136 ; x stride % 32 == 8 -> 72
#define WSTR 136
#define XSTR 72
#define W_STAGE_WORDS (KC * WSTR)            // 8704
#define X_STAGE_WORDS (TOKS * XSTR)          // 4608
#define STAGE_WORDS   (W_STAGE_WORDS + X_STAGE_WORDS)   // 13312
#define STAGE_BYTES   (STAGE_WORDS * 4)                 // 53248
#define W_STAGE_BYTES (W_STAGE_WORDS * 4)               // 34816
#define SMEM_BYTES    (STAGES * STAGE_BYTES)            // 106496

__device__ float g_xtf[TOKS * INF];            // tf32-rounded x, k-pair-interleaved
__device__ float g_xsum[TOKS];
__device__ float g_part[SPLITK * TOKS * OUTF]; // split-K partials (14.7MB)

static __device__ __forceinline__ uint32_t f2tf(float f) {
    uint32_t r;
    asm("cvt.rna.tf32.f32 %0, %1;" : "=r"(r) : "f"(f));
    return r;
}
static __device__ __forceinline__ uint32_t smem_u32(const void* p) {
    uint32_t a;
    asm("{ .reg .u64 t; cvta.to.shared.u64 t, %1; cvt.u32.u64 %0, t; }" : "=r"(a) : "l"(p));
    return a;
}
static __device__ __forceinline__ void cpasync16(uint32_t dst, const void* src) {
    asm volatile("cp.async.cg.shared.global [%0], [%1], 16;" :: "r"(dst), "l"(src));
}
static __device__ __forceinline__ void mma8(float* d, const uint32_t* a, const uint32_t* b) {
    asm volatile(
        "mma.sync.aligned.m16n8k8.row.col.f32.tf32.tf32.f32 "
        "{%0,%1,%2,%3}, {%4,%5,%6,%7}, {%8,%9}, {%0,%1,%2,%3};"
        : "+f"(d[0]), "+f"(d[1]), "+f"(d[2]), "+f"(d[3])
        : "r"(a[0]), "r"(a[1]), "r"(a[2]), "r"(a[3]), "r"(b[0]), "r"(b[1]));
}

// ---------- prep: x -> tf32, k-pair-interleave; per-token row sums ----------
// within each 8-block: original j stored at (j&3)*2 + (j>>2) -> (k,k+4) adjacent
__global__ void __launch_bounds__(256) prep_kernel(const float* __restrict__ x) {
    const int row = blockIdx.x;
    const int t = threadIdx.x;
    const float* xr = x + row * INF;
    float s = 0.f;
    #pragma unroll
    for (int i = 0; i < INF / 256; ++i) {
        const int k = t + i * 256;
        const float v = xr[k];
        s += v;
        const int j = k & 7;
        const int pos = (k & ~7) + ((j & 3) * 2 + (j >> 2));
        g_xtf[row * INF + pos] = __uint_as_float(f2tf(v));
    }
    #pragma unroll
    for (int off = 16; off; off >>= 1) s += __shfl_xor_sync(0xffffffffu, s, off);
    __shared__ float red[8];
    if ((t & 31) == 0) red[t >> 5] = s;
    __syncthreads();
    if (t < 8) {
        float v = red[t];
        #pragma unroll
        for (int off = 4; off; off >>= 1) v += __shfl_xor_sync(0xffu, v, off);
        if (t == 0) g_xsum[row] = v;
    }
}

// ---------- main GEMM (one split-K work unit per CTA) ----------
__global__ void __launch_bounds__(256, 2)
qbits_kernel(const int* __restrict__ W, const float* __restrict__ scales)
{
    extern __shared__ uint32_t smem[];
    const uint32_t sbase = smem_u32(smem);
    const int tid  = threadIdx.x;
    const int lane = tid & 31;
    const int warp = tid >> 5;          // 0..7
    const int wn   = warp;              // N: 16 cols each (warp tile m64n16)
    const int tile  = blockIdx.x % NTILES;
    const int split = blockIdx.x / NTILES;
    const int obase = tile * NTILE;
    const int kbase = split * KPER;

    // copy geometry (256 threads)
    const int*   wsrc = W + obase + (lane << 2);
    const float* xsrc = g_xtf + (tid >> 2) * INF + ((tid & 3) << 4);
    const uint32_t wdst_off = (uint32_t)((warp * WSTR + (lane << 2)) * 4);
    const uint32_t xdst_off = (uint32_t)(W_STAGE_BYTES +
                              (((tid >> 2) * XSTR + ((tid & 3) << 4)) * 4));

    float acc[4][2][4];   // [mt 0..3][nt 0..1][frag] scaled accumulators
    float accg[4][2][4];  // per-group raw accumulators
    #pragma unroll
    for (int mt = 0; mt < 4; ++mt)
        #pragma unroll
        for (int nt = 0; nt < 2; ++nt)
            #pragma unroll
            for (int j = 0; j < 4; ++j) { acc[mt][nt][j] = 0.f; accg[mt][nt][j] = 0.f; }

    auto issue = [&](int c, int s) {
        const int k0 = kbase + c * KC;
        const uint32_t wb = sbase + (uint32_t)(s * STAGE_BYTES);
        #pragma unroll
        for (int p = 0; p < 8; ++p)
            cpasync16(wb + wdst_off + (uint32_t)(p * 8 * WSTR * 4),
                      wsrc + (k0 + warp + 8 * p) * OUTF);
        #pragma unroll
        for (int i = 0; i < 4; ++i)
            cpasync16(wb + xdst_off + (uint32_t)(i * 16), xsrc + k0 + i * 4);
        asm volatile("cp.async.commit_group;" ::: "memory");
    };

    issue(0, 0);

    float2 sc2[2];        // per-D-column scales (cols wn*16 + nt*8 + 2*(lane&3)+{0,1})
    int st = 0;
    for (int c = 0; c < NCHUNK; ++c) {
        asm volatile("cp.async.wait_group 0;" ::: "memory");
        __syncthreads();
        if (c + 1 < NCHUNK) issue(c + 1, st ^ 1);

        if ((c & 1) == 0) {   // group start: fetch D-column scales
            const int g = split * (KPER / 128) + (c >> 1);
            const float* srow = scales + g * OUTF + obase + wn * 16 + 2 * (lane & 3);
            #pragma unroll
            for (int nt = 0; nt < 2; ++nt)
                sc2[nt] = __ldg((const float2*)(srow + nt * 8));
        }

        const uint32_t* ws  = smem + st * STAGE_WORDS;
        const float*    xsm = (const float*)(ws + W_STAGE_WORDS);

        #pragma unroll
        for (int ks = 0; ks < 8; ++ks) {
            const int kp = ks * 8 + 2 * (lane & 3);   // interleaved pair offset
            const int kk = ks * 8 + (lane & 3);
            uint32_t a[4][4];
            #pragma unroll
            for (int mt = 0; mt < 4; ++mt) {
                const int r = mt * 16 + (lane >> 2);
                const float2 p0 = *(const float2*)(xsm + r * XSTR + kp);        // (a0,a2)
                const float2 p1 = *(const float2*)(xsm + (r + 8) * XSTR + kp);  // (a1,a3)
                a[mt][0] = __float_as_uint(p0.x);
                a[mt][1] = __float_as_uint(p1.x);
                a[mt][2] = __float_as_uint(p0.y);
                a[mt][3] = __float_as_uint(p1.y);
            }
            #pragma unroll
            for (int nt = 0; nt < 2; ++nt) {
                const int col = wn * 16 + nt * 8 + (lane >> 2);
                const int w0 = (int)ws[kk * WSTR + col];
                const int w1 = (int)ws[(kk + 4) * WSTR + col];
                uint32_t bb[2];
                bb[0] = __float_as_uint((float)w0);   // exact in tf32
                bb[1] = __float_as_uint((float)w1);
                #pragma unroll
                for (int mt = 0; mt < 4; ++mt)
                    mma8(accg[mt][nt], a[mt], bb);
            }
        }

        if (c & 1) {          // group end: fold per-D-column scale, reset raw acc
            #pragma unroll
            for (int mt = 0; mt < 4; ++mt)
                #pragma unroll
                for (int nt = 0; nt < 2; ++nt) {
                    acc[mt][nt][0] = fmaf(sc2[nt].x, accg[mt][nt][0], acc[mt][nt][0]);
                    acc[mt][nt][1] = fmaf(sc2[nt].y, accg[mt][nt][1], acc[mt][nt][1]);
                    acc[mt][nt][2] = fmaf(sc2[nt].x, accg[mt][nt][2], acc[mt][nt][2]);
                    acc[mt][nt][3] = fmaf(sc2[nt].y, accg[mt][nt][3], acc[mt][nt][3]);
                    accg[mt][nt][0] = 0.f; accg[mt][nt][1] = 0.f;
                    accg[mt][nt][2] = 0.f; accg[mt][nt][3] = 0.f;
                }
        }
        st ^= 1;
    }

    // ---- epilogue: write partial tile (reduce kernel adds bias/u) ----
    float* part = g_part + split * (TOKS * OUTF);
    #pragma unroll
    for (int mt = 0; mt < 4; ++mt) {
        #pragma unroll
        for (int jr = 0; jr < 2; ++jr) {
            const int row = mt * 16 + (lane >> 2) + jr * 8;
            #pragma unroll
            for (int nt = 0; nt < 2; ++nt) {
                const int col = obase + wn * 16 + nt * 8 + 2 * (lane & 3);
                float2 o2;
                o2.x = acc[mt][nt][jr * 2 + 0];
                o2.y = acc[mt][nt][jr * 2 + 1];
                *(float2*)(part + row * OUTF + col) = o2;
            }
        }
    }
}

// ---------- reduce: out = sum(partials) + bias + xsum*u ----------
__global__ void __launch_bounds__(256)
reduce_kernel(const float* __restrict__ u, const float* __restrict__ bias,
              float* __restrict__ out)
{
    const int idx = blockIdx.x * 256 + threadIdx.x;       // over float4 units
    const int t   = idx / (OUTF / 4);
    const int c4  = (idx % (OUTF / 4)) * 4;
    const float xs = g_xsum[t];
    const int base = t * OUTF + c4;
    float4 s0 = *(const float4*)(g_part + 0 * TOKS * OUTF + base);
    float4 s1 = *(const float4*)(g_part + 1 * TOKS * OUTF + base);
    float4 s2 = *(const float4*)(g_part + 2 * TOKS * OUTF + base);
    float4 s3 = *(const float4*)(g_part + 3 * TOKS * OUTF + base);
    const float4 bv = *(const float4*)(bias + c4);
    const float4 uv = *(const float4*)(u + c4);
    float4 r;
    r.x = (s0.x + s1.x) + (s2.x + s3.x) + bv.x + xs * uv.x;
    r.y = (s0.y + s1.y) + (s2.y + s3.y) + bv.y + xs * uv.y;
    r.z = (s0.z + s1.z) + (s2.z + s3.z) + bv.z + xs * uv.z;
    r.w = (s0.w + s1.w) + (s2.w + s3.w) + bv.w + xs * uv.w;
    *(float4*)(out + base) = r;
}

extern "C" void kernel_launch(void* const* d_in, const int* in_sizes, int n_in,
                              void* d_out, int out_size) {
    const float* x  = (const float*)d_in[0];
    const int*   W  = (const int*)d_in[1];
    const float* sc = (const float*)d_in[2];
    const float* u  = (const float*)d_in[3];
    const float* b  = (const float*)d_in[4];
    float* out = (float*)d_out;

    cudaFuncSetAttribute(qbits_kernel, cudaFuncAttributeMaxDynamicSharedMemorySize,
                         SMEM_BYTES);
    prep_kernel<<<TOKS, 256>>>(x);
    qbits_kernel<<<NCTA, 256, SMEM_BYTES>>>(W, sc);
    reduce_kernel<<<(TOKS * OUTF / 4) / 256, 256>>>(u, b, out);
}